// round 2
// baseline (speedup 1.0000x reference)
#include <cuda_runtime.h>
#include <cuda_bf16.h>

// Problem constants
#define NWALK 4096
#define NIN   24      // NPART*NDIM = 8*3
#define HID   256
#define WPW   2       // walkers per warp
#define NWARP 8       // warps per block
#define WPB   (NWARP * WPW)   // 16 walkers per block
#define TPB   (NWARP * 32)    // 256 threads

// out[w] = -1/2 * ( lap log|psi| + |grad log|psi||^2 ) for
// log|psi|(z) = W2 . tanh(z W1 + b1) + b2
//
// Closed form:
//   a_j = sum_i z_i W1[i,j] + b1_j ; h_j = tanh(a_j) ; t_j = (1-h_j^2) W2_j
//   grad_i = sum_j W1[i,j] t_j
//   lap    = sum_j (-2 h_j t_j) * S_j,  S_j = sum_i W1[i,j]^2
__global__ __launch_bounds__(TPB)
void kinetic_kernel(const float* __restrict__ x,
                    const float* __restrict__ W1,
                    const float* __restrict__ b1,
                    const float* __restrict__ W2,
                    float* __restrict__ out)
{
    __shared__ float sW1[NIN * HID];   // 24 KB, row i contiguous in j
    __shared__ float sB1[HID];
    __shared__ float sW2[HID];
    __shared__ float sS[HID];
    __shared__ float sX[WPB][NIN];

    const int t = threadIdx.x;

    // ---- cooperative loads (coalesced) ----
#pragma unroll
    for (int i = 0; i < NIN; i++)
        sW1[i * HID + t] = W1[i * HID + t];
    sB1[t] = b1[t];
    sW2[t] = W2[t];
    {
        int base = blockIdx.x * (WPB * NIN);
#pragma unroll
        for (int e = t; e < WPB * NIN; e += TPB)
            sX[e / NIN][e % NIN] = x[base + e];
    }
    __syncthreads();

    // ---- per-column S_j = sum_i W1[i,j]^2 (thread t owns column j=t) ----
    {
        float s0 = 0.f, s1 = 0.f, s2 = 0.f, s3 = 0.f;
#pragma unroll
        for (int i = 0; i < NIN; i += 4) {
            float w0 = sW1[(i + 0) * HID + t];
            float w1 = sW1[(i + 1) * HID + t];
            float w2 = sW1[(i + 2) * HID + t];
            float w3 = sW1[(i + 3) * HID + t];
            s0 = fmaf(w0, w0, s0);
            s1 = fmaf(w1, w1, s1);
            s2 = fmaf(w2, w2, s2);
            s3 = fmaf(w3, w3, s3);
        }
        sS[t] = (s0 + s1) + (s2 + s3);
    }
    __syncthreads();

    const int warp = t >> 5;
    const int lane = t & 31;

    // each warp handles walkers: warp*WPW + {0,1}
    float z[WPW][NIN];
#pragma unroll
    for (int wk = 0; wk < WPW; wk++)
#pragma unroll
        for (int i = 0; i < NIN; i++)
            z[wk][i] = sX[warp * WPW + wk][i];

    float g[WPW][NIN];
#pragma unroll
    for (int wk = 0; wk < WPW; wk++)
#pragma unroll
        for (int i = 0; i < NIN; i++)
            g[wk][i] = 0.f;
    float lap[WPW];
#pragma unroll
    for (int wk = 0; wk < WPW; wk++) lap[wk] = 0.f;

    // Each lane owns 8 hidden units: j = lane + 32*k
    for (int k = 0; k < HID / 32; k++) {
        const int j = lane + 32 * k;

        // cache W1 column once; reuse across both walkers and both passes
        float w[NIN];
#pragma unroll
        for (int i = 0; i < NIN; i++) w[i] = sW1[i * HID + j];

        const float b = sB1[j];
        const float w2j = sW2[j];
        const float sj = sS[j];

#pragma unroll
        for (int wk = 0; wk < WPW; wk++) {
            // a_j with 4 split accumulators (break the RAW chain)
            float a0 = 0.f, a1 = 0.f, a2 = 0.f, a3 = 0.f;
#pragma unroll
            for (int i = 0; i < NIN; i += 4) {
                a0 = fmaf(z[wk][i + 0], w[i + 0], a0);
                a1 = fmaf(z[wk][i + 1], w[i + 1], a1);
                a2 = fmaf(z[wk][i + 2], w[i + 2], a2);
                a3 = fmaf(z[wk][i + 3], w[i + 3], a3);
            }
            float a = ((a0 + a1) + (a2 + a3)) + b;

            // accurate tanh via expf (MUFU EX2-based, ~1e-6 rel err)
            float e  = __expf(-2.0f * fabsf(a));
            float h  = __fdividef(1.0f - e, 1.0f + e);
            h = copysignf(h, a);

            float tj = (1.0f - h * h) * w2j;
            lap[wk] = fmaf(-2.0f * h * tj, sj, lap[wk]);

#pragma unroll
            for (int i = 0; i < NIN; i++)
                g[wk][i] = fmaf(w[i], tj, g[wk][i]);
        }
    }

    // ---- warp butterfly reduction per walker: lap + 24 gradient comps ----
#pragma unroll
    for (int wk = 0; wk < WPW; wk++) {
#pragma unroll
        for (int off = 16; off; off >>= 1) {
            lap[wk] += __shfl_xor_sync(0xffffffffu, lap[wk], off);
#pragma unroll
            for (int i = 0; i < NIN; i++)
                g[wk][i] += __shfl_xor_sync(0xffffffffu, g[wk][i], off);
        }
        if (lane == 0) {
            float q0 = 0.f, q1 = 0.f, q2 = 0.f, q3 = 0.f;
#pragma unroll
            for (int i = 0; i < NIN; i += 4) {
                q0 = fmaf(g[wk][i + 0], g[wk][i + 0], q0);
                q1 = fmaf(g[wk][i + 1], g[wk][i + 1], q1);
                q2 = fmaf(g[wk][i + 2], g[wk][i + 2], q2);
                q3 = fmaf(g[wk][i + 3], g[wk][i + 3], q3);
            }
            float gsq = (q0 + q1) + (q2 + q3);
            out[blockIdx.x * WPB + warp * WPW + wk] = -0.5f * (lap[wk] + gsq);
        }
    }
}

extern "C" void kernel_launch(void* const* d_in, const int* in_sizes, int n_in,
                              void* d_out, int out_size)
{
    const float* x  = (const float*)d_in[0];
    const float* W1 = (const float*)d_in[1];
    const float* b1 = (const float*)d_in[2];
    const float* W2 = (const float*)d_in[3];
    // d_in[4] = b2 : no effect on derivatives
    float* out = (float*)d_out;

    kinetic_kernel<<<NWALK / WPB, TPB>>>(x, W1, b1, W2, out);
}

// round 5
// speedup vs baseline: 1.1895x; 1.1895x over previous
#include <cuda_runtime.h>
#include <cuda_bf16.h>

// Problem constants
#define NWALK 4096
#define NIN   24      // NPART*NDIM = 8*3
#define HID   256
#define NWARP 8       // warps per block
#define TPB   (NWARP * 32)    // 256 threads
#define WPB   (NWARP * 2)     // 16 walkers per block (2 per warp, one per half-warp)
#define NCHUNK (HID / 16)     // 16 hidden units per lane

// out[w] = -1/2 * ( lap log|psi| + |grad log|psi||^2 ) for
// log|psi|(z) = W2 . tanh(z W1 + b1) + b2
//
// Closed form:
//   a_j = sum_i z_i W1[i,j] + b1_j ; h_j = tanh(a_j) ; t_j = (1-h_j^2) W2_j
//   grad_i = sum_j W1[i,j] t_j
//   lap    = sum_j (-2 h_j t_j) * S_j,  S_j = sum_i W1[i,j]^2
//
// Mapping: half-warp per walker. Lanes 0-15 -> walker (2*warp), lanes 16-31 ->
// walker (2*warp+1). Lane's sublane s owns hidden units j = s + 16*chunk.
// Both halves read the same j columns -> 64B LDS + broadcast, conflict-free.
__global__ __launch_bounds__(TPB, 2)
void kinetic_kernel(const float* __restrict__ x,
                    const float* __restrict__ W1,
                    const float* __restrict__ b1,
                    const float* __restrict__ W2,
                    float* __restrict__ out)
{
    __shared__ float sW1[NIN * HID];   // 24 KB, row i contiguous in j
    __shared__ float sB1[HID];
    __shared__ float sW2[HID];
    __shared__ float sS[HID];
    __shared__ float sX[WPB][NIN];

    const int t = threadIdx.x;

    // ---- cooperative loads (coalesced) ----
#pragma unroll
    for (int i = 0; i < NIN; i++)
        sW1[i * HID + t] = W1[i * HID + t];
    sB1[t] = b1[t];
    sW2[t] = W2[t];
    {
        int base = blockIdx.x * (WPB * NIN);
#pragma unroll
        for (int e = t; e < WPB * NIN; e += TPB)
            sX[e / NIN][e % NIN] = x[base + e];
    }
    __syncthreads();

    // ---- per-column S_j = sum_i W1[i,j]^2 (thread t owns column j=t) ----
    {
        float s0 = 0.f, s1 = 0.f, s2 = 0.f, s3 = 0.f;
#pragma unroll
        for (int i = 0; i < NIN; i += 4) {
            float w0 = sW1[(i + 0) * HID + t];
            float w1 = sW1[(i + 1) * HID + t];
            float w2 = sW1[(i + 2) * HID + t];
            float w3 = sW1[(i + 3) * HID + t];
            s0 = fmaf(w0, w0, s0);
            s1 = fmaf(w1, w1, s1);
            s2 = fmaf(w2, w2, s2);
            s3 = fmaf(w3, w3, s3);
        }
        sS[t] = (s0 + s1) + (s2 + s3);
    }
    __syncthreads();

    const int warp = t >> 5;
    const int lane = t & 31;
    const int half = lane >> 4;      // which walker within the warp
    const int s    = lane & 15;      // sublane within half-warp
    const int wkr  = warp * 2 + half;

    // walker coordinates (broadcast LDS -> registers)
    float z[NIN];
#pragma unroll
    for (int i = 0; i < NIN; i++) z[i] = sX[wkr][i];

    float g[NIN];
#pragma unroll
    for (int i = 0; i < NIN; i++) g[i] = 0.f;
    float lap = 0.f;

    // Each lane owns 16 hidden units: j = s + 16*chunk
    // (no outer unroll: keeps exactly one w[24] column cache live ->
    //  ~100 regs, safely under the 128-reg/2-blocks-per-SM budget)
    for (int k = 0; k < NCHUNK; k++) {
        const int j = s + 16 * k;

        // cache W1 column (reused for 'a' pass and 'g' pass)
        float w[NIN];
#pragma unroll
        for (int i = 0; i < NIN; i++) w[i] = sW1[i * HID + j];

        // a_j with 4 split accumulators (break the RAW chain)
        float a0 = 0.f, a1 = 0.f, a2 = 0.f, a3 = 0.f;
#pragma unroll
        for (int i = 0; i < NIN; i += 4) {
            a0 = fmaf(z[i + 0], w[i + 0], a0);
            a1 = fmaf(z[i + 1], w[i + 1], a1);
            a2 = fmaf(z[i + 2], w[i + 2], a2);
            a3 = fmaf(z[i + 3], w[i + 3], a3);
        }
        float a = ((a0 + a1) + (a2 + a3)) + sB1[j];

        // accurate tanh via expf (MUFU EX2-based, ~1e-6 rel err)
        float e  = __expf(-2.0f * fabsf(a));
        float h  = __fdividef(1.0f - e, 1.0f + e);
        h = copysignf(h, a);

        float tj = (1.0f - h * h) * sW2[j];
        lap = fmaf(-2.0f * h * tj, sS[j], lap);

#pragma unroll
        for (int i = 0; i < NIN; i++)
            g[i] = fmaf(w[i], tj, g[i]);
    }

    // ---- butterfly reduction within each half-warp (both walkers at once) ----
#pragma unroll
    for (int off = 8; off; off >>= 1) {
        lap += __shfl_xor_sync(0xffffffffu, lap, off);
#pragma unroll
        for (int i = 0; i < NIN; i++)
            g[i] += __shfl_xor_sync(0xffffffffu, g[i], off);
    }

    // every lane in the half now holds the full sums
    if (s == 0) {
        float q0 = 0.f, q1 = 0.f, q2 = 0.f, q3 = 0.f;
#pragma unroll
        for (int i = 0; i < NIN; i += 4) {
            q0 = fmaf(g[i + 0], g[i + 0], q0);
            q1 = fmaf(g[i + 1], g[i + 1], q1);
            q2 = fmaf(g[i + 2], g[i + 2], q2);
            q3 = fmaf(g[i + 3], g[i + 3], q3);
        }
        float gsq = (q0 + q1) + (q2 + q3);
        out[blockIdx.x * WPB + wkr] = -0.5f * (lap + gsq);
    }
}

extern "C" void kernel_launch(void* const* d_in, const int* in_sizes, int n_in,
                              void* d_out, int out_size)
{
    const float* x  = (const float*)d_in[0];
    const float* W1 = (const float*)d_in[1];
    const float* b1 = (const float*)d_in[2];
    const float* W2 = (const float*)d_in[3];
    // d_in[4] = b2 : no effect on derivatives
    float* out = (float*)d_out;

    kinetic_kernel<<<NWALK / WPB, TPB>>>(x, W1, b1, W2, out);
}